// round 1
// baseline (speedup 1.0000x reference)
#include <cuda_runtime.h>
#include <cuda_bf16.h>

// -------- constants from reference --------
#define EPS_F      1e-07f
#define FN_PENALTY 10.0f
#define W_CLASS 1.0f
#define W_BBOX  5.0f
#define W_GIOU  2.0f
#define W_CUT   3.0f

// -------- device scratch (no allocations allowed) --------
__device__ double g_acc[4];   // focal, bbox, giou, bce sums
__device__ int    g_lab64;    // 1 if labels are int64, 0 if int32

// ---------------------------------------------------------------
// Kernel 0: zero accumulators + detect label dtype.
// If labels are int64 (little-endian, values 0..3), every odd 32-bit
// word of the first 256 elements is 0. For int32 labels those words
// are random labels in [0,4): P(all 256 == 0) = 4^-256 ~ 0.
// ---------------------------------------------------------------
__global__ void init_detect_kernel(const int* __restrict__ labels_w, int n)
{
    if (threadIdx.x == 0 && blockIdx.x == 0) {
        g_acc[0] = 0.0; g_acc[1] = 0.0; g_acc[2] = 0.0; g_acc[3] = 0.0;
        int nchk = n < 256 ? n : 256;
        int all_zero = 1;
        for (int i = 0; i < nchk; ++i) {
            if (labels_w[2 * i + 1] != 0) { all_zero = 0; break; }
        }
        g_lab64 = all_zero;
    }
}

// validate_and_fix from the reference
__device__ __forceinline__ float4 fix_box(float4 b)
{
    bool invalid = (b.x > b.z) || (b.y > b.w);
    if (invalid) {
        b.x = fmaxf(b.x, 0.0f); b.y = fmaxf(b.y, 0.0f);
        b.z = fmaxf(b.z, 0.0f); b.w = fmaxf(b.w, 0.0f);
    }
    b.z = fmaxf(b.z, b.x + 1e-6f);
    b.w = fmaxf(b.w, b.y + 1e-6f);
    return b;
}

// ---------------------------------------------------------------
// Kernel 1: fused per-element losses + reduction
// ---------------------------------------------------------------
__global__ void __launch_bounds__(256)
fused_loss_kernel(const float4* __restrict__ logits,
                  const int*    __restrict__ labels_w,
                  const float4* __restrict__ pboxes,
                  const float4* __restrict__ tboxes,
                  const float*  __restrict__ cut_logits,
                  const float*  __restrict__ cut_targets,
                  int n)
{
    const int lab64 = g_lab64;
    float s_focal = 0.0f, s_bbox = 0.0f, s_giou = 0.0f, s_bce = 0.0f;

    const int stride = gridDim.x * blockDim.x;
    for (int i = blockIdx.x * blockDim.x + threadIdx.x; i < n; i += stride) {
        // ---------------- focal (4-class softmax CE) ----------------
        float4 L = __ldg(&logits[i]);
        int t = lab64 ? __ldg(&labels_w[2 * i]) : __ldg(&labels_w[i]);

        float m  = fmaxf(fmaxf(L.x, L.y), fmaxf(L.z, L.w));
        float s  = __expf(L.x - m) + __expf(L.y - m)
                 + __expf(L.z - m) + __expf(L.w - m);
        float lt = (t == 0) ? L.x : (t == 1) ? L.y : (t == 2) ? L.z : L.w;
        float ce = __logf(s) - (lt - m);
        float pt = __expf(-ce);
        float omp = 1.0f - pt;
        s_focal += omp * omp * ce;

        // ---------------- bbox L1 ----------------
        float4 pb = __ldg(&pboxes[i]);
        float4 tb = __ldg(&tboxes[i]);
        s_bbox += fabsf(pb.x - tb.x) + fabsf(pb.y - tb.y)
                + fabsf(pb.z - tb.z) + fabsf(pb.w - tb.w);

        // ---------------- GIoU ----------------
        float4 b1 = fix_box(pb);
        float4 b2 = fix_box(tb);
        float area1 = (b1.z - b1.x) * (b1.w - b1.y);
        float area2 = (b2.z - b2.x) * (b2.w - b2.y);
        float iw = fmaxf(fminf(b1.z, b2.z) - fmaxf(b1.x, b2.x), 0.0f);
        float ih = fmaxf(fminf(b1.w, b2.w) - fmaxf(b1.y, b2.y), 0.0f);
        float inter = iw * ih;
        float uni   = area1 + area2 - inter;
        float iou   = inter / (uni + EPS_F);
        float ew = fmaxf(fmaxf(b1.z, b2.z) - fminf(b1.x, b2.x), 0.0f);
        float eh = fmaxf(fmaxf(b1.w, b2.w) - fminf(b1.y, b2.y), 0.0f);
        float enc = ew * eh;
        float giou = iou - (enc - uni) / (enc + EPS_F);
        s_giou += fmaxf(1.0f - giou, 0.0f);

        // ---------------- weighted BCE ----------------
        float cl = __ldg(&cut_logits[i]);
        float ct = __ldg(&cut_targets[i]);
        float bce = fmaxf(cl, 0.0f) - cl * ct + log1pf(__expf(-fabsf(cl)));
        // sigmoid(cl) < 0.5  <=>  cl < 0
        float w = ((ct == 1.0f) && (cl < 0.0f)) ? FN_PENALTY : 1.0f;
        s_bce += bce * w;
    }

    // -------- warp reduce --------
    #pragma unroll
    for (int off = 16; off > 0; off >>= 1) {
        s_focal += __shfl_down_sync(0xffffffffu, s_focal, off);
        s_bbox  += __shfl_down_sync(0xffffffffu, s_bbox,  off);
        s_giou  += __shfl_down_sync(0xffffffffu, s_giou,  off);
        s_bce   += __shfl_down_sync(0xffffffffu, s_bce,   off);
    }

    __shared__ float sh[4][8];
    int lane = threadIdx.x & 31;
    int wid  = threadIdx.x >> 5;
    if (lane == 0) {
        sh[0][wid] = s_focal; sh[1][wid] = s_bbox;
        sh[2][wid] = s_giou;  sh[3][wid] = s_bce;
    }
    __syncthreads();

    if (wid == 0) {
        float v0 = (lane < 8) ? sh[0][lane] : 0.0f;
        float v1 = (lane < 8) ? sh[1][lane] : 0.0f;
        float v2 = (lane < 8) ? sh[2][lane] : 0.0f;
        float v3 = (lane < 8) ? sh[3][lane] : 0.0f;
        #pragma unroll
        for (int off = 4; off > 0; off >>= 1) {
            v0 += __shfl_down_sync(0xffffffffu, v0, off);
            v1 += __shfl_down_sync(0xffffffffu, v1, off);
            v2 += __shfl_down_sync(0xffffffffu, v2, off);
            v3 += __shfl_down_sync(0xffffffffu, v3, off);
        }
        if (lane == 0) {
            atomicAdd(&g_acc[0], (double)v0);
            atomicAdd(&g_acc[1], (double)v1);
            atomicAdd(&g_acc[2], (double)v2);
            atomicAdd(&g_acc[3], (double)v3);
        }
    }
}

// ---------------------------------------------------------------
// Kernel 2: finalize the 5 output scalars
// ---------------------------------------------------------------
__global__ void finalize_kernel(float* __restrict__ out, int n)
{
    if (threadIdx.x == 0 && blockIdx.x == 0) {
        double inv_n = 1.0 / (double)n;
        float lc = fmaxf((float)(g_acc[0] * inv_n), 0.0f);
        float lb = fmaxf((float)(g_acc[1] * inv_n * 0.25), 0.0f);
        float lg = fmaxf((float)(g_acc[2] * inv_n), 0.0f);
        float lu = fmaxf((float)(g_acc[3] * inv_n), 0.0f);
        out[0] = W_CLASS * lc + W_BBOX * lb + W_GIOU * lg + W_CUT * lu;
        out[1] = lc;
        out[2] = lb;
        out[3] = lg;
        out[4] = lu;
    }
}

// ---------------------------------------------------------------
// Inputs (metadata order):
//   0 pred_logits    float32 [N,4]
//   1 target_labels  int64/int32 [N]
//   2 pred_boxes     float32 [N,4]
//   3 target_boxes   float32 [N,4]
//   4 cutting_logits float32 [N]
//   5 cutting_targets float32 [N]
// output: 5 x float32
// ---------------------------------------------------------------
extern "C" void kernel_launch(void* const* d_in, const int* in_sizes, int n_in,
                              void* d_out, int out_size)
{
    const float4* logits   = (const float4*)d_in[0];
    const int*    labels_w = (const int*)   d_in[1];
    const float4* pboxes   = (const float4*)d_in[2];
    const float4* tboxes   = (const float4*)d_in[3];
    const float*  cl       = (const float*) d_in[4];
    const float*  ct       = (const float*) d_in[5];
    float*        out      = (float*)d_out;

    const int n = in_sizes[1];   // element count of target_labels = N

    init_detect_kernel<<<1, 32>>>(labels_w, n);

    const int threads = 256;
    int blocks = (n + threads - 1) / threads;
    if (blocks > 2368) blocks = 2368;   // 16 blocks/SM upper bound on 148 SMs
    fused_loss_kernel<<<blocks, threads>>>(logits, labels_w, pboxes, tboxes,
                                           cl, ct, n);

    finalize_kernel<<<1, 32>>>(out, n);
}